// round 6
// baseline (speedup 1.0000x reference)
#include <cuda_runtime.h>
#include <cstdint>

// Shape (fixed): u[B=16, T=1024, H=2048] f32, alpha[H], beta[H], seed int32
#define BB 16
#define TT 1024
#define HH 2048
#define HC 8            // channels per CTA (= warps per CTA)
#define NTHR 256
#define FULLM 0xFFFFFFFFu

#define TILE_FLOATS (TT * HC)    // 8192 floats = 32 KB

// XOR-swizzled tile layout (see R4): conflict-free column gathers.
__device__ __forceinline__ int swz(int t, int c) {
    int L = t >> 5;
    return (L << 8) + ((((t & 31) << 3) + c) ^ L);
}

__device__ __forceinline__ unsigned rotl32(unsigned x, int r) {
    return __funnelshift_l(x, x, r);
}

// Integer add on the FMA pipe (IMAD a*one+b); `one` is an opaque param (=1).
__device__ __forceinline__ unsigned addi(unsigned a, unsigned one, unsigned b) {
    unsigned r;
    asm("mad.lo.u32 %0, %1, %2, %3;" : "=r"(r) : "r"(a), "r"(one), "r"(b));
    return r;
}

// XLA f32 tanh (Eigen generic_fast_tanh_float), plain mul/add (no contraction).
__device__ __forceinline__ float tanh_xla(float x) {
    float ax = fabsf(x);
    float xc = fminf(fmaxf(x, -7.90531110763549805f), 7.90531110763549805f);
    float x2 = __fmul_rn(xc, xc);
    float np = __fadd_rn(__fmul_rn(x2, -2.76076847742355e-16f), 2.00018790482477e-13f);
    np = __fadd_rn(__fmul_rn(x2, np), -8.60467152213735e-11f);
    np = __fadd_rn(__fmul_rn(x2, np),  5.12229709037114e-08f);
    np = __fadd_rn(__fmul_rn(x2, np),  1.48572235717979e-05f);
    np = __fadd_rn(__fmul_rn(x2, np),  6.37261928875436e-04f);
    np = __fadd_rn(__fmul_rn(x2, np),  4.89352455891786e-03f);
    float num = __fmul_rn(xc, np);
    float dp = __fadd_rn(__fmul_rn(x2, 1.19825839466702e-06f), 1.18534705686654e-04f);
    dp = __fadd_rn(__fmul_rn(x2, dp), 2.26843463243900e-03f);
    dp = __fadd_rn(__fmul_rn(x2, dp), 4.89352518554385e-03f);
    float t = __fdiv_rn(num, dp);
    return (ax < 0.0004f) ? x : t;
}

// Exact jax.lax.associative_scan tree over 1024 elems/channel:
// in-place register Blelloch (levels 0-4) + warp-shuffle Blelloch (5-9).
__device__ __forceinline__ void tree_scan(float (&v)[32], const float* A, int lane) {
    #pragma unroll
    for (int s = 0; s < 5; s++) {
        const int h = 1 << s, st = h << 1;
        #pragma unroll
        for (int p = st - 1; p < 32; p += st)
            v[p] = __fadd_rn(__fmul_rn(A[s], v[p - h]), v[p]);
    }
    float w = v[31];
    #pragma unroll
    for (int m = 0; m < 5; m++) {
        float t = __shfl_up_sync(FULLM, w, 1 << m);
        if ((lane & ((2 << m) - 1)) == ((2 << m) - 1))
            w = __fadd_rn(__fmul_rn(A[5 + m], t), w);
    }
    #pragma unroll
    for (int m = 3; m >= 0; m--) {
        float t = __shfl_up_sync(FULLM, w, 1 << m);
        if (((lane & ((2 << m) - 1)) == ((1 << m) - 1)) && (lane >= (2 << m)))
            w = __fadd_rn(__fmul_rn(A[5 + m], t), w);
    }
    float P = __shfl_up_sync(FULLM, w, 1);
    if (lane == 0) P = 0.0f;
    v[31] = w;
    #pragma unroll
    for (int s = 4; s >= 0; s--) {
        const int h = 1 << s, st = h << 1;
        #pragma unroll
        for (int p = h - 1; p < 32; p += st) {
            float left = (p < st) ? P : v[p - h];
            v[p] = __fadd_rn(__fmul_rn(A[s], left), v[p]);
        }
    }
}

__global__ void __launch_bounds__(NTHR)
cubalif_kernel(const float* __restrict__ u,
               const float* __restrict__ alpha,
               const float* __restrict__ beta,
               const int*   __restrict__ seedp,
               float* __restrict__ out,
               unsigned one) {
    __shared__ float S[TILE_FLOATS];

    const int tid  = threadIdx.x;
    const int lane = tid & 31;
    const int wrp  = tid >> 5;            // warp id in CTA = channel for scan
    const int b    = blockIdx.x >> 8;
    const int h0   = (blockIdx.x & 255) * HC;

    // ---- stage u tile [T][8] into swizzled smem + zero-fill out tile ----
    const float4* up4 = reinterpret_cast<const float4*>(u + ((size_t)b * TT) * HH + h0);
    float* outp = out + ((size_t)b * TT) * HH + h0;
    const float4 z4 = make_float4(0.f, 0.f, 0.f, 0.f);
    #pragma unroll
    for (int k = 0; k < TILE_FLOATS / 4 / NTHR; k++) {   // 8 iters
        int i4 = k * NTHR + tid;
        int t = i4 >> 1, q = i4 & 1;
        float4 d = up4[(size_t)t * (HH / 4) + q];
        int c0 = q * 4;
        S[swz(t, c0 + 0)] = d.x;
        S[swz(t, c0 + 1)] = d.y;
        S[swz(t, c0 + 2)] = d.z;
        S[swz(t, c0 + 3)] = d.w;
        *reinterpret_cast<float4*>(outp + (size_t)t * HH + c0) = z4;
    }
    __syncthreads();

    // ---- gather 32 time steps of channel wrp (conflict-free) ----
    float v[32];
    #pragma unroll
    for (int j = 0; j < 32; j++)
        v[j] = S[(lane << 8) + (((j << 3) + wrp) ^ lane)];

    // ---- decay powers + two scans (bit-exact vs JAX) ----
    float A[10];
    A[0] = fminf(fmaxf(alpha[h0 + wrp], 0.0f), 1.0f);
    #pragma unroll
    for (int s = 1; s < 10; s++) A[s] = __fmul_rn(A[s - 1], A[s - 1]);
    tree_scan(v, A, lane);                // synaptic current

    A[0] = fminf(fmaxf(beta[h0 + wrp], 0.0f), 1.0f);
    #pragma unroll
    for (int s = 1; s < 10; s++) A[s] = __fmul_rn(A[s - 1], A[s - 1]);
    tree_scan(v, A, lane);                // membrane potential V

    // ---- write V back to this warp's channel slots ----
    #pragma unroll
    for (int j = 0; j < 32; j++)
        S[(lane << 8) + (((j << 3) + wrp) ^ lane)] = v[j];
    __syncthreads();

    // ================= Phase A: p for all, gather p>0 masks =================
    // Warp w owns flat tile region f in [w*1024, (w+1)*1024), f = t*8 + c.
    const int wtile = wrp << 10;
    unsigned m_own = 0u;                  // lane j keeps the mask of pass j
    #pragma unroll
    for (int j = 0; j < 32; j++) {
        int f = wtile + (j << 5) + lane;
        int t = f >> 3, c = f & 7;
        int sa = swz(t, c);
        float V = S[sa];
        float U = __fadd_rn(V, -1.0f);                       // V - THRESHOLD
        float cv  = cosf(__fmul_rn(6.2831855f, U));          // cos(f32(2pi)*U)
        float th  = tanh_xla(__fmul_rn(50.0f, U));           // logistic(100U)
        float sig = __fadd_rn(__fmul_rn(0.5f, th), 0.5f);
        float p   = fmaxf(__fmul_rn(cv, sig), 0.0f);
        S[sa] = p;                                           // overwrite V with p
        unsigned mask = __ballot_sync(FULLM, p > 0.0f);
        if (lane == j) m_own = mask;
    }

    // ---- warp prefix over per-group counts ----
    int cnt  = __popc(m_own);
    int incl = cnt;
    #pragma unroll
    for (int s = 1; s < 32; s <<= 1) {
        int tsh = __shfl_up_sync(FULLM, incl, s);
        if (lane >= s) incl += tsh;
    }
    int E = incl - cnt;                                      // exclusive prefix
    int total = __shfl_sync(FULLM, incl, 31);
    __syncwarp();   // order Phase A stores before Phase B overwrites

    // ================= Phase B: threefry only where p > 0 =================
    const unsigned k2   = (unsigned)seedp[0];    // key=(0,seed): ks0=0
    const unsigned ks1  = k2;
    const unsigned ks2v = k2 ^ 0x1BD11BDAu;

    for (int s0 = 0; s0 < total; s0 += 32) {
        int r = s0 + lane;
        bool act = r < total;
        int rr = act ? r : (total - 1);
        // find group g = largest g with E_g <= rr (E nondecreasing)
        int g = 0;
        #pragma unroll
        for (int st = 16; st >= 1; st >>= 1) {
            int cand = g + st;
            int Ec = __shfl_sync(FULLM, E, cand & 31);
            if (cand < 32 && Ec <= rr) g = cand;
        }
        int rank = rr - __shfl_sync(FULLM, E, g);
        unsigned mg = __shfl_sync(FULLM, m_own, g);
        int bit = __fns(mg, 0, rank + 1);
        int f = wtile + (g << 5) + bit;
        int t = f >> 3, c = f & 7;
        float p = S[swz(t, c)];
        unsigned gi = (unsigned)(b * TT + t) * (unsigned)HH + (unsigned)(h0 + c);

        // threefry2x32(key=(0,seed), counts=(0, gi)); fold out0^out1
        unsigned x0 = 0u;
        unsigned x1 = gi + ks1;
        #define TFR(r_) { x0 = addi(x1, one, x0); x1 = rotl32(x1, (r_)); x1 ^= x0; }
        TFR(13) TFR(15) TFR(26) TFR(6)   x0 += ks1;  x1 += ks2v + 1u;
        TFR(17) TFR(29) TFR(16) TFR(24)  x0 += ks2v; x1 += 2u;
        TFR(13) TFR(15) TFR(26) TFR(6)                x1 += ks1 + 3u;
        TFR(17) TFR(29) TFR(16) TFR(24)  x0 += ks1;  x1 += ks2v + 4u;
        TFR(13) TFR(15) TFR(26) TFR(6)   x0 += ks2v; x1 += 5u;
        #undef TFR
        unsigned bits = x0 ^ x1;
        float uf = __fadd_rn(__uint_as_float((bits >> 9) | 0x3F800000u), -1.0f);
        if (act && uf < p) out[gi] = 1.0f;   // overwrite the zero
    }
}

extern "C" void kernel_launch(void* const* d_in, const int* in_sizes, int n_in,
                              void* d_out, int out_size) {
    const float* u     = (const float*)d_in[0];
    const float* alpha = (const float*)d_in[1];
    const float* beta  = (const float*)d_in[2];
    const int*   seed  = (const int*)d_in[3];
    float* out = (float*)d_out;
    (void)in_sizes; (void)n_in; (void)out_size;

    dim3 grid(BB * (HH / HC));   // 4096 CTAs
    cubalif_kernel<<<grid, NTHR>>>(u, alpha, beta, seed, out, 1u);
}

// round 7
// speedup vs baseline: 1.1685x; 1.1685x over previous
#include <cuda_runtime.h>
#include <cstdint>

// Shape (fixed): u[B=16, T=1024, H=2048] f32, alpha[H], beta[H], seed int32
#define BB 16
#define TT 1024
#define HH 2048
#define HC 8            // channels per CTA (= warps per CTA)
#define NTHR 256
#define FULLM 0xFFFFFFFFu

#define TILE_FLOATS (TT * HC)    // 8192 floats = 32 KB

// XOR-swizzled tile layout (see R4): conflict-free column gathers.
__device__ __forceinline__ int swz(int t, int c) {
    int L = t >> 5;
    return (L << 8) + ((((t & 31) << 3) + c) ^ L);
}

__device__ __forceinline__ unsigned rotl32(unsigned x, int r) {
    return __funnelshift_l(x, x, r);
}

// Integer add on the FMA pipe (IMAD a*one+b); `one` is an opaque param (=1).
__device__ __forceinline__ unsigned addi(unsigned a, unsigned one, unsigned b) {
    unsigned r;
    asm("mad.lo.u32 %0, %1, %2, %3;" : "=r"(r) : "r"(a), "r"(one), "r"(b));
    return r;
}

// XLA f32 tanh (Eigen generic_fast_tanh_float), plain mul/add (no contraction).
__device__ __forceinline__ float tanh_xla(float x) {
    float ax = fabsf(x);
    float xc = fminf(fmaxf(x, -7.90531110763549805f), 7.90531110763549805f);
    float x2 = __fmul_rn(xc, xc);
    float np = __fadd_rn(__fmul_rn(x2, -2.76076847742355e-16f), 2.00018790482477e-13f);
    np = __fadd_rn(__fmul_rn(x2, np), -8.60467152213735e-11f);
    np = __fadd_rn(__fmul_rn(x2, np),  5.12229709037114e-08f);
    np = __fadd_rn(__fmul_rn(x2, np),  1.48572235717979e-05f);
    np = __fadd_rn(__fmul_rn(x2, np),  6.37261928875436e-04f);
    np = __fadd_rn(__fmul_rn(x2, np),  4.89352455891786e-03f);
    float num = __fmul_rn(xc, np);
    float dp = __fadd_rn(__fmul_rn(x2, 1.19825839466702e-06f), 1.18534705686654e-04f);
    dp = __fadd_rn(__fmul_rn(x2, dp), 2.26843463243900e-03f);
    dp = __fadd_rn(__fmul_rn(x2, dp), 4.89352518554385e-03f);
    float t = __fdiv_rn(num, dp);
    return (ax < 0.0004f) ? x : t;
}

// Exact jax.lax.associative_scan tree over 1024 elems/channel:
// in-place register Blelloch (levels 0-4) + warp-shuffle Blelloch (5-9).
__device__ __forceinline__ void tree_scan(float (&v)[32], const float* A, int lane) {
    #pragma unroll
    for (int s = 0; s < 5; s++) {
        const int h = 1 << s, st = h << 1;
        #pragma unroll
        for (int p = st - 1; p < 32; p += st)
            v[p] = __fadd_rn(__fmul_rn(A[s], v[p - h]), v[p]);
    }
    float w = v[31];
    #pragma unroll
    for (int m = 0; m < 5; m++) {
        float t = __shfl_up_sync(FULLM, w, 1 << m);
        if ((lane & ((2 << m) - 1)) == ((2 << m) - 1))
            w = __fadd_rn(__fmul_rn(A[5 + m], t), w);
    }
    #pragma unroll
    for (int m = 3; m >= 0; m--) {
        float t = __shfl_up_sync(FULLM, w, 1 << m);
        if (((lane & ((2 << m) - 1)) == ((1 << m) - 1)) && (lane >= (2 << m)))
            w = __fadd_rn(__fmul_rn(A[5 + m], t), w);
    }
    float P = __shfl_up_sync(FULLM, w, 1);
    if (lane == 0) P = 0.0f;
    v[31] = w;
    #pragma unroll
    for (int s = 4; s >= 0; s--) {
        const int h = 1 << s, st = h << 1;
        #pragma unroll
        for (int p = h - 1; p < 32; p += st) {
            float left = (p < st) ? P : v[p - h];
            v[p] = __fadd_rn(__fmul_rn(A[s], left), v[p]);
        }
    }
}

__global__ void __launch_bounds__(NTHR)
cubalif_kernel(const float* __restrict__ u,
               const float* __restrict__ alpha,
               const float* __restrict__ beta,
               const int*   __restrict__ seedp,
               float* __restrict__ out,
               unsigned one) {
    __shared__ float S[TILE_FLOATS];                 // 32 KB
    __shared__ unsigned short Lst[TILE_FLOATS];      // 16 KB compacted indices

    const int tid  = threadIdx.x;
    const int lane = tid & 31;
    const int wrp  = tid >> 5;            // warp id in CTA = channel for scan
    const int b    = blockIdx.x >> 8;
    const int h0   = (blockIdx.x & 255) * HC;

    // ---- stage u tile [T][8] into swizzled smem + zero-fill out tile ----
    const float4* up4 = reinterpret_cast<const float4*>(u + ((size_t)b * TT) * HH + h0);
    float* outp = out + ((size_t)b * TT) * HH + h0;
    const float4 z4 = make_float4(0.f, 0.f, 0.f, 0.f);
    #pragma unroll
    for (int k = 0; k < TILE_FLOATS / 4 / NTHR; k++) {   // 8 iters
        int i4 = k * NTHR + tid;
        int t = i4 >> 1, q = i4 & 1;
        float4 d = up4[(size_t)t * (HH / 4) + q];
        int c0 = q * 4;
        S[swz(t, c0 + 0)] = d.x;
        S[swz(t, c0 + 1)] = d.y;
        S[swz(t, c0 + 2)] = d.z;
        S[swz(t, c0 + 3)] = d.w;
        *reinterpret_cast<float4*>(outp + (size_t)t * HH + c0) = z4;
    }
    __syncthreads();

    // ---- gather 32 time steps of channel wrp (conflict-free) ----
    float v[32];
    #pragma unroll
    for (int j = 0; j < 32; j++)
        v[j] = S[(lane << 8) + (((j << 3) + wrp) ^ lane)];

    // ---- decay powers + two scans (bit-exact vs JAX) ----
    float A[10];
    A[0] = fminf(fmaxf(alpha[h0 + wrp], 0.0f), 1.0f);
    #pragma unroll
    for (int s = 1; s < 10; s++) A[s] = __fmul_rn(A[s - 1], A[s - 1]);
    tree_scan(v, A, lane);                // synaptic current

    A[0] = fminf(fmaxf(beta[h0 + wrp], 0.0f), 1.0f);
    #pragma unroll
    for (int s = 1; s < 10; s++) A[s] = __fmul_rn(A[s - 1], A[s - 1]);
    tree_scan(v, A, lane);                // membrane potential V

    // ---- write V back to this warp's channel slots ----
    #pragma unroll
    for (int j = 0; j < 32; j++)
        S[(lane << 8) + (((j << 3) + wrp) ^ lane)] = v[j];
    __syncthreads();

    // ========== Phase A: p for all; compact indices of p>0 into Lst ==========
    // Warp w owns flat tile region f in [w*1024, (w+1)*1024), f = t*8 + c.
    const int wtile = wrp << 10;
    int cnt_run = 0;                      // uniform running count
    #pragma unroll 4
    for (int j = 0; j < 32; j++) {
        int f = wtile + (j << 5) + lane;
        int t = f >> 3, c = f & 7;
        int sa = swz(t, c);
        float V = S[sa];
        float U = __fadd_rn(V, -1.0f);                       // V - THRESHOLD
        float cv  = cosf(__fmul_rn(6.2831855f, U));          // cos(f32(2pi)*U)
        float th  = tanh_xla(__fmul_rn(50.0f, U));           // logistic(100U)
        float sig = __fadd_rn(__fmul_rn(0.5f, th), 0.5f);
        float p   = fmaxf(__fmul_rn(cv, sig), 0.0f);
        S[sa] = p;                                           // overwrite V with p
        bool act = p > 0.0f;
        unsigned mask = __ballot_sync(FULLM, act);
        if (act) {
            int pos = cnt_run + __popc(mask & ((1u << lane) - 1u));
            Lst[wtile + pos] = (unsigned short)f;             // tile-local index
        }
        cnt_run += __popc(mask);
    }
    int total = cnt_run;
    __syncwarp();   // cross-lane visibility of S (p) and Lst within the warp

    // ========== Phase B: threefry only where p > 0 ==========
    const unsigned k2   = (unsigned)seedp[0];    // key=(0,seed): ks0=0
    const unsigned ks1  = k2;
    const unsigned ks2v = k2 ^ 0x1BD11BDAu;
    const unsigned Cbase = (unsigned)(b * TT) * (unsigned)HH + (unsigned)h0;

    for (int s0 = 0; s0 < total; s0 += 32) {
        int r = s0 + lane;
        bool act = r < total;
        int rr = act ? r : (total - 1);
        int f = (int)Lst[wtile + rr];
        int t = f >> 3, c = f & 7;
        float p = S[swz(t, c)];
        unsigned gi = Cbase + (unsigned)t * (unsigned)HH + (unsigned)c;

        // threefry2x32(key=(0,seed), counts=(0, gi)); fold out0^out1
        unsigned x0 = 0u;
        unsigned x1 = gi + ks1;
        #define TFR(r_) { x0 = addi(x1, one, x0); x1 = rotl32(x1, (r_)); x1 ^= x0; }
        TFR(13) TFR(15) TFR(26) TFR(6)   x0 += ks1;  x1 += ks2v + 1u;
        TFR(17) TFR(29) TFR(16) TFR(24)  x0 += ks2v; x1 += 2u;
        TFR(13) TFR(15) TFR(26) TFR(6)                x1 += ks1 + 3u;
        TFR(17) TFR(29) TFR(16) TFR(24)  x0 += ks1;  x1 += ks2v + 4u;
        TFR(13) TFR(15) TFR(26) TFR(6)   x0 += ks2v; x1 += 5u;
        #undef TFR
        unsigned bits = x0 ^ x1;
        float uf = __fadd_rn(__uint_as_float((bits >> 9) | 0x3F800000u), -1.0f);
        if (act && uf < p) out[gi] = 1.0f;   // overwrite the zero
    }
}

extern "C" void kernel_launch(void* const* d_in, const int* in_sizes, int n_in,
                              void* d_out, int out_size) {
    const float* u     = (const float*)d_in[0];
    const float* alpha = (const float*)d_in[1];
    const float* beta  = (const float*)d_in[2];
    const int*   seed  = (const int*)d_in[3];
    float* out = (float*)d_out;
    (void)in_sizes; (void)n_in; (void)out_size;

    dim3 grid(BB * (HH / HC));   // 4096 CTAs
    cubalif_kernel<<<grid, NTHR>>>(u, alpha, beta, seed, out, 1u);
}